// round 5
// baseline (speedup 1.0000x reference)
#include <cuda_runtime.h>

#define Vdim   96
#define Kdim   20
#define Bdim   256
#define Ddim   1024
#define NIJ    9
#define GROUPS 144      // 3*3*4*2*2
#define VK     1920     // Vdim*Kdim

// mega kernel geometry
#define BPB    64               // b's per yphi block
#define SPLITS (Bdim / BPB)     // 4
#define NPHI   (GROUPS * SPLITS)   // 576 yphi-role blocks
#define DCHUNK 20               // d's per Y block
#define NYB    52               // ceil(1024/20)
#define NY     (NIJ * NYB)      // 468 Y-role blocks
#define TMEGA  480              // threads (yphi: 480*float4 = one VK slab; Y: 20d x 24q)

// ---- scratch (static device globals — no runtime allocation) ----
__device__ float  g_ytr[NIJ * Ddim];     // sum over (e,n,c,v) of Y  -> [ij][d]
__device__ float  g_eT0[VK];             // exp(_T0)
__device__ float  g_lt[VK];              // sigmoid(_t)
__device__ float  g_lr[VK];              // sigmoid(_r)
__device__ float  g_invZ[NIJ * Kdim];    // 1 / sum_v eT0*wt*wr
__device__ float  g_lqt[3 * Kdim];       // log qt rows (third row = 0)
__device__ float  g_lqr[3 * Kdim];
__device__ float  g_L3[16 * Kdim];       // log pe + log pn + log pc per (enc,k)
__device__ float  g_L1[NIJ * VK];        // log T + log qt + log qr per (ij,v,k)
__device__ float  g_Wb[NIJ * Bdim];      // sum over (enc,v,k) of yphi -> [ij][b]
__device__ double g_loss;

// ---------------------------------------------------------------------------
// Kernel 1: elementwise tables + zero Wb/loss (grid-parallel, tiny)
// ---------------------------------------------------------------------------
__global__ __launch_bounds__(TMEGA) void k_prepTab(
    const float* __restrict__ T0p, const float* __restrict__ tp,
    const float* __restrict__ rp)
{
    int i = blockIdx.x * TMEGA + threadIdx.x;   // grid 4 -> 1920 threads
    if (i < VK) {
        g_eT0[i] = __expf(T0p[i]);
        g_lt[i]  = 1.f / (1.f + __expf(-tp[i]));
        g_lr[i]  = 1.f / (1.f + __expf(-rp[i]));
    }
    for (int j = i; j < NIJ * Bdim; j += 4 * TMEGA) g_Wb[j] = 0.f;
    if (i == 0) g_loss = 0.0;
}

// ---------------------------------------------------------------------------
// Kernel 2: tiny cross-element reductions + small log tables (1 block)
// ---------------------------------------------------------------------------
__global__ __launch_bounds__(1024) void k_prepZ(
    const float* __restrict__ ep, const float* __restrict__ enp,
    const float* __restrict__ ecp)
{
    __shared__ float se[VK], st[VK], sr[VK];
    __shared__ float scolsum[Kdim];
    __shared__ float sZraw[NIJ * Kdim];
    int t = threadIdx.x, lane = t & 31, w = t >> 5;

    for (int i = t; i < VK; i += 1024) { se[i] = g_eT0[i]; st[i] = g_lt[i]; sr[i] = g_lr[i]; }
    __syncthreads();

    // column sums of eT0 over V (warp per column)
    if (w < Kdim) {
        float s = 0.f;
        for (int v = lane; v < Vdim; v += 32) s += se[v * Kdim + w];
#pragma unroll
        for (int off = 16; off; off >>= 1) s += __shfl_down_sync(0xffffffffu, s, off);
        if (lane == 0) scolsum[w] = s;
    }
    // raw Z[ij][k] (warp per output)
    for (int o = w; o < NIJ * Kdim; o += 32) {
        int ij = o / Kdim, k = o - ij * Kdim, i = ij / 3, j = ij % 3;
        float s = 0.f;
        for (int v = lane; v < Vdim; v += 32) {
            int r = v * Kdim + k;
            float wt = (i == 0) ? st[r] : (i == 1) ? 1.f - st[r] : 1.f;
            float wr = (j == 0) ? sr[r] : (j == 1) ? 1.f - sr[r] : 1.f;
            s += se[r] * wt * wr;
        }
#pragma unroll
        for (int off = 16; off; off >>= 1) s += __shfl_down_sync(0xffffffffu, s, off);
        if (lane == 0) sZraw[o] = s;
    }
    __syncthreads();

    if (t < NIJ * Kdim) g_invZ[t] = 1.f / sZraw[t];

    if (t < Kdim) {
        float inv = 1.f / scolsum[t];
        float pt = sZraw[2 * Kdim + t] * inv;   // ij = (0,2): wt=lt, wr=1
        float pr = sZraw[6 * Kdim + t] * inv;   // ij = (2,0): wt=1, wr=lr
        g_lqt[t] = __logf(pt); g_lqt[Kdim + t] = __logf(1.f - pt); g_lqt[2 * Kdim + t] = 0.f;
        g_lqr[t] = __logf(pr); g_lqr[Kdim + t] = __logf(1.f - pr); g_lqr[2 * Kdim + t] = 0.f;
        float lpe[4], lpn[2], lpc[2]; float s, l;
        s = 0.f; for (int e = 0; e < 4; ++e) s += __expf(ep[e * Kdim + t]);
        l = __logf(s);
        for (int e = 0; e < 4; ++e) lpe[e] = ep[e * Kdim + t] - l;
        s = 0.f; for (int n = 0; n < 2; ++n) s += __expf(enp[n * Kdim + t]);
        l = __logf(s);
        for (int n = 0; n < 2; ++n) lpn[n] = enp[n * Kdim + t] - l;
        s = 0.f; for (int c = 0; c < 2; ++c) s += __expf(ecp[c * Kdim + t]);
        l = __logf(s);
        for (int c = 0; c < 2; ++c) lpc[c] = ecp[c * Kdim + t] - l;
        for (int enc = 0; enc < 16; ++enc)
            g_L3[enc * Kdim + t] = lpe[enc >> 2] + lpn[(enc >> 1) & 1] + lpc[enc & 1];
    }
}

// ---------------------------------------------------------------------------
// Kernel 3: L1[ij][v][k] = log T + log qt + log qr   (grid-parallel logs)
// ---------------------------------------------------------------------------
__global__ __launch_bounds__(384) void k_prepL1() {
    int idx = blockIdx.x * 384 + threadIdx.x;
    if (idx >= NIJ * VK) return;
    int ij  = idx / VK;
    int rem = idx - ij * VK;
    int k   = rem % Kdim;
    int i = ij / 3, j = ij % 3;
    float lt = g_lt[rem], lr = g_lr[rem];
    float wt = (i == 0) ? lt : (i == 1) ? 1.f - lt : 1.f;
    float wr = (j == 0) ? lr : (j == 1) ? 1.f - lr : 1.f;
    float tv = g_eT0[rem] * wt * wr * g_invZ[ij * Kdim + k];   // softmax norm cancels
    g_L1[idx] = __logf(tv) + g_lqt[i * Kdim + k] + g_lqr[j * Kdim + k];
}

// ---------------------------------------------------------------------------
// Kernel 4 (MEGA): one DRAM-bound wave over yphi (283MB) AND Y (56.6MB).
//  blocks [0, NPHI): stream yphi, dot against L1+L3, accumulate Wb[ij][b]
//  blocks [NPHI, NPHI+NY): reduce Y -> ytr
// ---------------------------------------------------------------------------
__global__ __launch_bounds__(TMEGA) void k_mega(
    const float* __restrict__ yphi, const float* __restrict__ Yv)
{
    int blk = blockIdx.x, t = threadIdx.x;
    if (blk < NPHI) {
        int group  = blk / SPLITS;             // ij*16 + enc
        int bsplit = blk - group * SPLITS;
        int ij = group >> 4, enc = group & 15;
        int lane = t & 31, w = t >> 5;

        __shared__ float  sL3[Kdim];
        __shared__ float  swb[BPB * 16];       // [b][warp] (15 warps, pad to 16)
        __shared__ double sred[TMEGA / 32];
        if (t < Kdim) sL3[t] = g_L3[enc * Kdim + t];
        __syncthreads();

        // fixed per-thread weights
        float4 wv = *(const float4*)(g_L1 + ij * VK + 4 * t);
        int kb = (4 * t) % Kdim;
        wv.x += sL3[kb]; wv.y += sL3[kb + 1]; wv.z += sL3[kb + 2]; wv.w += sL3[kb + 3];

        const float4* p = (const float4*)(yphi + (size_t)group * (Bdim * VK)
                                               + (size_t)bsplit * BPB * VK) + t;
        float acc = 0.f;
#pragma unroll 8
        for (int b = 0; b < BPB; ++b) {
            float4 x = p[(size_t)b * (VK / 4)];
            acc += x.x * wv.x; acc += x.y * wv.y;
            acc += x.z * wv.z; acc += x.w * wv.w;
            float s = (x.x + x.y) + (x.z + x.w);
#pragma unroll
            for (int off = 16; off; off >>= 1) s += __shfl_down_sync(0xffffffffu, s, off);
            if (lane == 0) swb[b * 16 + w] = s;
        }
        __syncthreads();
        // Wb: one atomic per b
        if (t < BPB) {
            float s = 0.f;
#pragma unroll
            for (int w2 = 0; w2 < TMEGA / 32; ++w2) s += swb[t * 16 + w2];
            atomicAdd(&g_Wb[ij * Bdim + bsplit * BPB + t], s);
        }
        // weighted-loss reduce
#pragma unroll
        for (int off = 16; off; off >>= 1) acc += __shfl_down_sync(0xffffffffu, acc, off);
        if (lane == 0) sred[w] = (double)acc;
        __syncthreads();
        if (t == 0) {
            double s = 0.0;
#pragma unroll
            for (int w2 = 0; w2 < TMEGA / 32; ++w2) s += sred[w2];
            atomicAdd(&g_loss, s);
        }
    } else {
        // ---- Y reduction role ----
        int yb    = blk - NPHI;
        int ij    = yb / NYB;
        int chunk = yb - ij * NYB;
        int d0 = chunk * DCHUNK;
        int dl = t / 24, vq = t - dl * 24;     // 20 d's x 24 float4
        int d  = d0 + dl;
        __shared__ float sY[TMEGA];
        float s = 0.f;
        if (d < Ddim) {
            const float4* q = (const float4*)Yv
                + (size_t)ij * (16 * Ddim * 24) + (size_t)d * 24 + vq;
#pragma unroll
            for (int enc = 0; enc < 16; ++enc) {
                float4 x = q[(size_t)enc * (Ddim * 24)];
                s += (x.x + x.y) + (x.z + x.w);
            }
        }
        sY[t] = s;
        __syncthreads();
        if (t < DCHUNK && d0 + t < Ddim) {
            float r = 0.f;
#pragma unroll
            for (int v = 0; v < 24; ++v) r += sY[t * 24 + v];
            g_ytr[ij * Ddim + d0 + t] = r;
        }
    }
}

// ---------------------------------------------------------------------------
// Kernel 5: finisher — log missing-rates + Wb dot + scale (1 block)
// ---------------------------------------------------------------------------
__global__ __launch_bounds__(256) void k_finish(
    const int* __restrict__ index, float* __restrict__ out)
{
    __shared__ double sred[256];
    int t = threadIdx.x;
    int d = index[t];
    float y[9];
#pragma unroll
    for (int ij = 0; ij < 9; ++ij) y[ij] = g_ytr[ij * Ddim + d];
    float tot = ((y[0] + y[1]) + (y[2] + y[3])) + ((y[4] + y[5]) + (y[6] + y[7])) + y[8];
    float inv = 1.f / tot;
    float lmr[4];
    lmr[0] = __logf((y[0] + y[1] + y[3] + y[4]) * inv);  // m00
    lmr[1] = __logf((y[2] + y[5]) * inv);                // m01
    lmr[2] = __logf((y[6] + y[7]) * inv);                // m10
    lmr[3] = __logf(y[8] * inv);                         // m11
    double acc = 0.0;
#pragma unroll
    for (int ij = 0; ij < 9; ++ij) {
        int i = ij / 3, j = ij % 3;
        int sel = ((i == 2) ? 2 : 0) + ((j == 2) ? 1 : 0);
        acc += (double)g_Wb[ij * Bdim + t] * (double)lmr[sel];
    }
    sred[t] = acc;
    __syncthreads();
    for (int off = 128; off; off >>= 1) {
        if (t < off) sred[t] += sred[t + off];
        __syncthreads();
    }
    if (t == 0) out[0] = (float)(-(g_loss + sred[0]) / (double)VK);
}

// ---------------------------------------------------------------------------
extern "C" void kernel_launch(void* const* d_in, const int* in_sizes, int n_in,
                              void* d_out, int out_size) {
    (void)in_sizes; (void)n_in; (void)out_size;
    const float* yphi = (const float*)d_in[0];
    const float* Yv   = (const float*)d_in[1];
    const float* T0p  = (const float*)d_in[2];
    const float* tp   = (const float*)d_in[3];
    const float* rp   = (const float*)d_in[4];
    const float* ep   = (const float*)d_in[5];
    const float* enp  = (const float*)d_in[6];
    const float* ecp  = (const float*)d_in[7];
    const int*   idx  = (const int*)d_in[8];
    float* out = (float*)d_out;

    k_prepTab<<<4, TMEGA>>>(T0p, tp, rp);
    k_prepZ<<<1, 1024>>>(ep, enp, ecp);
    k_prepL1<<<(NIJ * VK + 383) / 384, 384>>>();
    k_mega<<<NPHI + NY, TMEGA>>>(yphi, Yv);
    k_finish<<<1, 256>>>(idx, out);
}